// round 12
// baseline (speedup 1.0000x reference)
#include <cuda_runtime.h>
#include <cuda_bf16.h>
#include <math.h>
#include <stdint.h>

#define BD   2
#define CINC 64
#define COUTC 64
#define HH   192
#define WW   192
#define DGC  8
#define CGC  8
#define KKC  9
#define HWC  (HH*WW)

#define RR 40     // staging region (16 + 2*RG)
#define RP 41     // padded row stride in cells
#define RG 12     // guard; global fallback covers |offset| > RG-1

#define NPAD 256            // conv N padded: 216 real rows + 40 zero rows
#define WCHUNK (NPAD*64*2)  // 32768 B per weight chunk plane

typedef unsigned long long u64;

__device__ __forceinline__ u64 pk2(float v) {
    u64 r; asm("mov.b64 %0, {%1,%1};" : "=l"(r) : "f"(v)); return r;
}
__device__ __forceinline__ void fma2(u64 &d, u64 a, u64 b) {
    asm("fma.rn.f32x2 %0, %1, %2, %0;" : "+l"(d) : "l"(a), "l"(b));
}
__device__ __forceinline__ float lo32(u64 v) { return __uint_as_float((unsigned)v); }
__device__ __forceinline__ float hi32(u64 v) { return __uint_as_float((unsigned)(v >> 32)); }

__device__ __forceinline__ uint32_t smem_u32(const void* p) {
    uint32_t a;
    asm("{ .reg .u64 t; cvta.to.shared.u64 t, %1; cvt.u32.u64 %0, t; }" : "=r"(a) : "l"(p));
    return a;
}

#define LDM_X4(r, addr) \
    asm volatile("ldmatrix.sync.aligned.m8n8.x4.shared.b16 {%0,%1,%2,%3}, [%4];" \
        : "=r"((r)[0]), "=r"((r)[1]), "=r"((r)[2]), "=r"((r)[3]) : "r"(addr))
#define LDM_X2(r, addr) \
    asm volatile("ldmatrix.sync.aligned.m8n8.x2.shared.b16 {%0,%1}, [%2];" \
        : "=r"((r)[0]), "=r"((r)[1]) : "r"(addr))
#define MMA16816(c, a, bb) \
    asm volatile("mma.sync.aligned.m16n8k16.row.col.f32.bf16.bf16.f32 " \
        "{%0,%1,%2,%3},{%4,%5,%6,%7},{%8,%9},{%0,%1,%2,%3};" \
        : "+f"((c)[0]), "+f"((c)[1]), "+f"((c)[2]), "+f"((c)[3]) \
        : "r"((a)[0]), "r"((a)[1]), "r"((a)[2]), "r"((a)[3]), \
          "r"((bb)[0]), "r"((bb)[1]))
#define CPASYNC16(dst, src) \
    asm volatile("cp.async.cg.shared.global [%0], [%1], 16;" :: "r"(dst), "l"(src))

// ---------------- scratch ---------------------------------------------------
__device__ float  g_x0t[BD*CINC*HWC];            // x0 repacked [B][DG][H*W][CG]
__device__ float4 g_par[BD*DGC*KKC*HWC];         // (dy, dx, mask, 0)
__device__ float  g_wt[DGC*KKC*CGC*COUTC];       // sample weights [g][k][c][o]
__device__ char   g_aih[(size_t)BD*288*9*16384]; // im2col hi, SW128 [px128][k64]
__device__ char   g_ail[(size_t)BD*288*9*16384]; // im2col lo
__device__ char   g_wbh[9*WCHUNK];               // conv W hi chunks [n256][k64] SW128
__device__ char   g_wbl[9*WCHUNK];               // conv W lo chunks

// ---------------- kernel T: repack x0 (8ch contiguous) ----------------------
__global__ void k_transpose(const float* __restrict__ x0) {
    int m = blockIdx.x * blockDim.x + threadIdx.x;
    if (m >= BD*DGC*HWC) return;
    int yx = m % HWC;
    int g  = (m / HWC) % DGC;
    int b  = m / (HWC*DGC);
    const float* src = x0 + ((size_t)(b*CINC + g*8)*HWC) + yx;
    float4 a, c;
    a.x = src[0*HWC]; a.y = src[1*HWC]; a.z = src[2*HWC]; a.w = src[3*HWC];
    c.x = src[4*HWC]; c.y = src[5*HWC]; c.z = src[6*HWC]; c.w = src[7*HWC];
    float4* dst = reinterpret_cast<float4*>(g_x0t + (size_t)m * 8);
    dst[0] = a; dst[1] = c;
}

// ---------------- kernel W: repack sample weight to [g][k][c][o] -------------
__global__ void k_wprep(const float* __restrict__ weight) {
    int m = blockIdx.x * blockDim.x + threadIdx.x;
    if (m >= DGC*KKC*CGC*COUTC) return;
    int o = m & 63;
    int r = m >> 6;
    int c = r & 7;
    int s = r >> 3;
    int k = s % 9, g = s / 9;
    g_wt[m] = weight[(o*CINC + g*8 + c)*KKC + k];
}

// ---------------- kernel WS: conv weights -> hi/lo bf16 chunks ---------------
__global__ void k_wsplit(const float* __restrict__ com_w) {
    int m = blockIdx.x * blockDim.x + threadIdx.x;
    if (m >= 9*NPAD*64) return;
    int ki = m & 63;
    int n  = (m >> 6) % NPAD;
    int cp = m / (NPAD*64);
    float w = 0.f;
    if (n < 216) {
        int kp = cp*64 + ki;
        int cin = kp / 9;
        int tap = kp - cin*9;
        int i = n / 3;
        int r = n - 3*i;
        int ch = (r == 0) ? 2*i : (r == 1) ? (2*i + 1) : (144 + i);
        w = com_w[ch*576 + cin*9 + tap];
    }
    __nv_bfloat16 h = __float2bfloat16(w);
    __nv_bfloat16 l = __float2bfloat16(w - __bfloat162float(h));
    uint32_t byte = (uint32_t)(n*64 + ki)*2;
    uint32_t sw = byte ^ ((byte >> 3) & 0x70);
    *(__nv_bfloat16*)(g_wbh + cp*WCHUNK + sw) = h;
    *(__nv_bfloat16*)(g_wbl + cp*WCHUNK + sw) = l;
}

// ---------------- kernel I: im2col (coalesced warp stores) -------------------
__global__ void __launch_bounds__(256, 1)
k_imcol(const float* __restrict__ x1) {
    __shared__ float xs[CINC*10*19];
    int blk = blockIdx.x;
    int tl  = blk % 288;
    int b   = blk / 288;
    int ty0 = (tl / 12) * 8;
    int tx0 = (tl % 12) * 16;
    int tid = threadIdx.x;

    for (int m = tid; m < CINC*10*18; m += 256) {
        int cin = m / 180;
        int rem = m % 180;
        int r = rem / 18, c = rem % 18;
        int gy = ty0 - 1 + r, gx = tx0 - 1 + c;
        float v = 0.f;
        if (gy >= 0 && gy < HH && gx >= 0 && gx < WW)
            v = x1[((b*CINC + cin)*HWC) + gy*WW + gx];
        xs[cin*190 + r*19 + c] = v;
    }
    __syncthreads();

    size_t base = (size_t)blk * 9 * 16384;
    for (int m = tid; m < 128*576; m += 256) {
        int px = m / 576;            // warp-uniform (576 % 32 == 0)
        int kp = m - px*576;
        int cin = kp / 9;
        int tap = kp - cin*9;
        int ti = tap / 3, tj = tap - ti*3;
        int pr = px >> 4, pc = px & 15;
        float v = xs[cin*190 + (pr + ti)*19 + (pc + tj)];
        __nv_bfloat16 h = __float2bfloat16(v);
        __nv_bfloat16 l = __float2bfloat16(v - __bfloat162float(h));
        int cp = kp >> 6;
        int ki = kp & 63;
        uint32_t byte = (uint32_t)(px*128 + ki*2);
        uint32_t sw = byte ^ ((byte >> 3) & 0x70);
        size_t off = base + (size_t)cp*16384 + sw;
        *(__nv_bfloat16*)(g_aih + off) = h;
        *(__nv_bfloat16*)(g_ail + off) = l;
    }
}

// ---------------- kernel G: HMMA conv GEMM, 512 thr, 16 warps ---------------
// CTA = 128 px x 216(256) ch. Warp grid 2M x 8N; warp tile 4 m16 x 4 n8.
// smem: A 2buf x 2plane x 16KB (0..65535) + W 2buf x 2plane x 32KB
//       (65536..196607). Epilogue stage [128][228] f32 aliases base.
struct ConvSmem { char bytes[196608]; };

__device__ __forceinline__ void conv_issue(uint32_t sb, int blk, int c, int buf, int tid) {
    size_t ab = ((size_t)(blk*9 + c)) * 16384;
    #pragma unroll
    for (int u = tid; u < 2048; u += 512) {
        int pl = u >> 10, ln = u & 1023;
        uint32_t d = sb + buf*32768 + pl*16384 + ln*16;
        const char* s = (pl ? g_ail : g_aih) + ab + (size_t)ln*16;
        CPASYNC16(d, s);
    }
    #pragma unroll
    for (int u = tid; u < 4096; u += 512) {
        int pl = u >> 11, ln = u & 2047;
        uint32_t d = sb + 65536 + buf*65536 + pl*32768 + ln*16;
        const char* s = (pl ? g_wbl : g_wbh) + c*WCHUNK + (size_t)ln*16;
        CPASYNC16(d, s);
    }
    asm volatile("cp.async.commit_group;" ::: "memory");
}

__device__ __forceinline__ void conv_pass(
    uint32_t Ap, uint32_t Wp,
    float (&acc)[4][4][4],
    const uint32_t (&a_row)[4], const uint32_t (&b_row)[4],
    uint32_t a_kb, uint32_t b_kb, uint32_t a_xor)
{
    #pragma unroll
    for (int ks = 0; ks < 4; ks++) {
        uint32_t kk = (uint32_t)ks * 32;
        uint32_t af[4][4];
        #pragma unroll
        for (int mt = 0; mt < 4; mt++)
            LDM_X4(af[mt], Ap + a_row[mt] + ((kk + a_kb) ^ a_xor));
        uint32_t bf[4][2];
        #pragma unroll
        for (int nt = 0; nt < 4; nt++)
            LDM_X2(bf[nt], Wp + b_row[nt] + ((kk + b_kb) ^ a_xor));
        #pragma unroll
        for (int mt = 0; mt < 4; mt++)
            #pragma unroll
            for (int nt = 0; nt < 4; nt++)
                MMA16816(acc[mt][nt], af[mt], bf[nt]);
    }
}

__global__ void __launch_bounds__(512, 1)
k_conv(const float* __restrict__ com_b,
       const float* __restrict__ pre_off,
       const float* __restrict__ pre_sim) {
    extern __shared__ ConvSmem smc[];
    uint32_t sb = smem_u32(smc);
    int tid  = threadIdx.x;
    int lane = tid & 31, wid = tid >> 5;
    int wm = wid & 1, wn = wid >> 1;        // 2M x 8N
    int b   = blockIdx.y;
    int tl  = blockIdx.x;
    int blk = b*288 + tl;
    int ty0 = (tl / 12) * 8;
    int tx0 = (tl % 12) * 16;

    uint32_t a_xor = (lane & 7) << 4;
    uint32_t a_kb  = (lane >> 4) << 4;
    uint32_t b_kb  = ((lane >> 3) & 1) << 4;
    uint32_t a_row[4], b_row[4];
    #pragma unroll
    for (int mt = 0; mt < 4; mt++)
        a_row[mt] = (uint32_t)(wm*64 + mt*16 + (lane & 15)) * 128;
    #pragma unroll
    for (int nt = 0; nt < 4; nt++)
        b_row[nt] = (uint32_t)(wn*32 + nt*8 + (lane & 7)) * 128;

    float acc[4][4][4];
    #pragma unroll
    for (int mt = 0; mt < 4; mt++)
        #pragma unroll
        for (int nt = 0; nt < 4; nt++)
            #pragma unroll
            for (int q = 0; q < 4; q++) acc[mt][nt][q] = 0.f;

    conv_issue(sb, blk, 0, 0, tid);

    for (int c = 0; c < 9; c++) {
        int buf = c & 1;
        if (c < 8) {
            conv_issue(sb, blk, c + 1, buf ^ 1, tid);
            asm volatile("cp.async.wait_group 1;" ::: "memory");
        } else {
            asm volatile("cp.async.wait_group 0;" ::: "memory");
        }
        __syncthreads();

        uint32_t Ah = sb + buf*32768;
        uint32_t Al = Ah + 16384;
        uint32_t Wh = sb + 65536 + buf*65536;
        uint32_t Wl = Wh + 32768;

        conv_pass(Ah, Wh, acc, a_row, b_row, a_kb, b_kb, a_xor);
        conv_pass(Ah, Wl, acc, a_row, b_row, a_kb, b_kb, a_xor);
        conv_pass(Al, Wh, acc, a_row, b_row, a_kb, b_kb, a_xor);

        __syncthreads();
    }

    float* os = (float*)smc;
    int gid = lane >> 2, tig = lane & 3;
    #pragma unroll
    for (int mt = 0; mt < 4; mt++) {
        int m0 = wm*64 + mt*16 + gid;
        #pragma unroll
        for (int nt = 0; nt < 4; nt++) {
            int n0 = wn*32 + nt*8 + tig*2;
            if (n0 < 216) {
                *(float2*)&os[m0*228 + n0]       = make_float2(acc[mt][nt][0], acc[mt][nt][1]);
                *(float2*)&os[(m0 + 8)*228 + n0] = make_float2(acc[mt][nt][2], acc[mt][nt][3]);
            }
        }
    }
    __syncthreads();

    for (int it = tid; it < 128*72; it += 512) {
        int px = it & 127;
        int i  = it >> 7;
        int k  = i % 9;
        int y  = ty0 + (px >> 4);
        int x  = tx0 + (px & 15);
        float o1 = os[px*228 + 3*i]     + com_b[2*i];
        float o2 = os[px*228 + 3*i + 1] + com_b[2*i + 1];
        float mr = os[px*228 + 3*i + 2] + com_b[144 + i];
        float2 po = ((const float2*)pre_off)[(b*9 + k)*HWC + y*WW + x];
        float dy = 10.f * tanhf(o1) + po.y;
        float dx = 10.f * tanhf(o2) + po.x;
        int idx = (b*72 + i)*HWC + y*WW + x;
        float sim = pre_sim[idx];
        float msk = 1.f / (1.f + expf(-mr * sim));
        g_par[idx] = make_float4(dy, dx, msk, 0.f);
    }
}

// ---------------- kernel S: sample + reduce; low-pressure q-outer reduce ----
__global__ void __launch_bounds__(256, 2)
k_sample(const float* __restrict__ bias,
         float* __restrict__ out) {
    extern __shared__ float sm[];
    float* xs  = sm;                    // [RR][RP][8]
    float* wsl = sm + RR*RP*8;          // [k][c][o]

    int b    = blockIdx.y;
    int tile = blockIdx.x;
    int ty0  = (tile / 12) * 16;
    int tx0  = (tile % 12) * 16;
    int tid  = threadIdx.x;
    int ty = tid >> 4, tx = tid & 15;
    int y = ty0 + ty, x = tx0 + tx;
    int ry0 = ty0 - RG, rx0 = tx0 - RG;

    u64 acc[32];
    #pragma unroll
    for (int q = 0; q < 32; q++) acc[q] = 0ull;

    for (int g = 0; g < DGC; g++) {
        const float* xb = g_x0t + (size_t)(b*DGC + g) * HWC * CGC;
        float4 prc = g_par[((b*72 + g*9)*HWC) + y*WW + x];
        __syncthreads();
        {
            const float4* wsrc = reinterpret_cast<const float4*>(g_wt + g*4608);
            float4* wdst = reinterpret_cast<float4*>(wsl);
            for (int m = tid; m < 1152; m += 256) wdst[m] = wsrc[m];
        }
        for (int m = tid; m < RR*RR*2; m += 256) {
            int cell = m >> 1, hh = m & 1;
            int rr = cell / RR, cc = cell % RR;
            int gy = ry0 + rr, gx = rx0 + cc;
            float4 v = make_float4(0.f, 0.f, 0.f, 0.f);
            if (gy >= 0 && gy < HH && gx >= 0 && gx < WW)
                v = *reinterpret_cast<const float4*>(xb + (size_t)(gy*WW + gx)*8 + hh*4);
            *reinterpret_cast<float4*>(xs + (rr*RP + cc)*8 + hh*4) = v;
        }
        __syncthreads();

        #pragma unroll 1
        for (int k = 0; k < KKC; k++) {
            int kn = (k < 8) ? (k + 1) : 8;
            float4 prn = g_par[((b*72 + g*9 + kn)*HWC) + y*WW + x];

            float dy = prc.x, dx = prc.y, mk = prc.z;
            float py = (float)(y - 1 + k/3) + dy;
            float px = (float)(x - 1 + k%3) + dx;
            float y0f = floorf(py), x0f = floorf(px);
            float ly = py - y0f,   lx = px - x0f;
            int iy0 = (int)y0f, ix0 = (int)x0f;

            u64 sv2[4] = {0ull, 0ull, 0ull, 0ull};
            #pragma unroll
            for (int cy = 0; cy < 2; cy++) {
                int yy = iy0 + cy;
                float wy = cy ? ly : (1.f - ly);
                #pragma unroll
                for (int cx = 0; cx < 2; cx++) {
                    int xx = ix0 + cx;
                    u64 wg2 = pk2(wy * (cx ? lx : (1.f - lx)));
                    int ry = yy - ry0, rx = xx - rx0;
                    if ((unsigned)ry < RR && (unsigned)rx < RR) {
                        const ulonglong2* pp =
                            reinterpret_cast<const ulonglong2*>(xs + (ry*RP + rx)*8);
                        ulonglong2 v0 = pp[0];
                        ulonglong2 v1 = pp[1];
                        fma2(sv2[0], wg2, v0.x);
                        fma2(sv2[1], wg2, v0.y);
                        fma2(sv2[2], wg2, v1.x);
                        fma2(sv2[3], wg2, v1.y);
                    } else if (yy >= 0 && yy < HH && xx >= 0 && xx < WW) {
                        const ulonglong2* pp =
                            reinterpret_cast<const ulonglong2*>(xb + (size_t)(yy*WW + xx)*8);
                        ulonglong2 v0 = pp[0];
                        ulonglong2 v1 = pp[1];
                        fma2(sv2[0], wg2, v0.x);
                        fma2(sv2[1], wg2, v0.y);
                        fma2(sv2[2], wg2, v1.x);
                        fma2(sv2[3], wg2, v1.y);
                    }
                }
            }

            u64 s2[8];
            #pragma unroll
            for (int c = 0; c < 8; c++) {
                u64 hv = sv2[c >> 1];
                float s = ((c & 1) ? hi32(hv) : lo32(hv)) * mk;
                s2[c] = pk2(s);
            }

            const float* wrow = wsl + k*512;
            #pragma unroll
            for (int q4 = 0; q4 < 16; q4++) {
                #pragma unroll
                for (int c = 0; c < 8; c++) {
                    ulonglong2 w = *reinterpret_cast<const ulonglong2*>(
                        wrow + c*64 + 4*q4);
                    fma2(acc[2*q4],     s2[c], w.x);
                    fma2(acc[2*q4 + 1], s2[c], w.y);
                }
            }
            prc = prn;
        }
    }

    #pragma unroll
    for (int q = 0; q < 32; q++) {
        out[((b*COUTC + 2*q)    *HH + y)*WW + x] = lo32(acc[q]) + bias[2*q];
        out[((b*COUTC + 2*q + 1)*HH + y)*WW + x] = hi32(acc[q]) + bias[2*q+1];
    }
}

// ---------------- launch ----------------------------------------------------
extern "C" void kernel_launch(void* const* d_in, const int* in_sizes, int n_in,
                              void* d_out, int out_size) {
    const float* x0      = (const float*)d_in[0];
    const float* x1      = (const float*)d_in[1];
    const float* pre_off = (const float*)d_in[2];
    const float* pre_sim = (const float*)d_in[3];
    const float* weight  = (const float*)d_in[4];
    const float* bias    = (const float*)d_in[5];
    const float* com_w   = (const float*)d_in[6];
    const float* com_b   = (const float*)d_in[7];
    float* out = (float*)d_out;

    cudaFuncSetAttribute(k_conv,   cudaFuncAttributeMaxDynamicSharedMemorySize, 196608);
    cudaFuncSetAttribute(k_sample, cudaFuncAttributeMaxDynamicSharedMemorySize, 70912);

    int totalT = BD*DGC*HWC;
    k_transpose<<<(totalT + 255) / 256, 256>>>(x0);
    k_wprep<<<(DGC*KKC*CGC*COUTC + 255) / 256, 256>>>(weight);
    k_wsplit<<<(9*NPAD*64 + 255) / 256, 256>>>(com_w);
    k_imcol<<<BD*288, 256>>>(x1);

    dim3 gridG(288, BD);
    k_conv<<<gridG, 512, 196608>>>(com_b, pre_off, pre_sim);

    dim3 gridS(144, BD);
    k_sample<<<gridS, 256, 70912>>>(bias, out);
}

// round 13
// speedup vs baseline: 1.1042x; 1.1042x over previous
#include <cuda_runtime.h>
#include <cuda_bf16.h>
#include <math.h>
#include <stdint.h>

#define BD   2
#define CINC 64
#define COUTC 64
#define HH   192
#define WW   192
#define DGC  8
#define CGC  8
#define KKC  9
#define HWC  (HH*WW)

#define RR 40     // staging region (16 + 2*RG)
#define RP 41     // padded row stride in cells
#define RG 12     // guard; global fallback covers |offset| > RG-1

#define NPAD 224            // conv N padded: 216 real rows + 8 zero rows
#define WCHUNK (NPAD*64*2)  // 28672 B per weight chunk plane

typedef unsigned long long u64;

__device__ __forceinline__ u64 pk2(float v) {
    u64 r; asm("mov.b64 %0, {%1,%1};" : "=l"(r) : "f"(v)); return r;
}
__device__ __forceinline__ void fma2(u64 &d, u64 a, u64 b) {
    asm("fma.rn.f32x2 %0, %1, %2, %0;" : "+l"(d) : "l"(a), "l"(b));
}
__device__ __forceinline__ float lo32(u64 v) { return __uint_as_float((unsigned)v); }
__device__ __forceinline__ float hi32(u64 v) { return __uint_as_float((unsigned)(v >> 32)); }

__device__ __forceinline__ uint32_t smem_u32(const void* p) {
    uint32_t a;
    asm("{ .reg .u64 t; cvta.to.shared.u64 t, %1; cvt.u32.u64 %0, t; }" : "=r"(a) : "l"(p));
    return a;
}

#define LDM_X4(r, addr) \
    asm volatile("ldmatrix.sync.aligned.m8n8.x4.shared.b16 {%0,%1,%2,%3}, [%4];" \
        : "=r"((r)[0]), "=r"((r)[1]), "=r"((r)[2]), "=r"((r)[3]) : "r"(addr))
#define LDM_X2(r, addr) \
    asm volatile("ldmatrix.sync.aligned.m8n8.x2.shared.b16 {%0,%1}, [%2];" \
        : "=r"((r)[0]), "=r"((r)[1]) : "r"(addr))
#define MMA16816(c, a, bb) \
    asm volatile("mma.sync.aligned.m16n8k16.row.col.f32.bf16.bf16.f32 " \
        "{%0,%1,%2,%3},{%4,%5,%6,%7},{%8,%9},{%0,%1,%2,%3};" \
        : "+f"((c)[0]), "+f"((c)[1]), "+f"((c)[2]), "+f"((c)[3]) \
        : "r"((a)[0]), "r"((a)[1]), "r"((a)[2]), "r"((a)[3]), \
          "r"((bb)[0]), "r"((bb)[1]))
#define CPASYNC16(dst, src) \
    asm volatile("cp.async.cg.shared.global [%0], [%1], 16;" :: "r"(dst), "l"(src))

// ---------------- scratch ---------------------------------------------------
__device__ float  g_x0t[BD*CINC*HWC];            // x0 repacked [B][DG][H*W][CG]
__device__ float4 g_par[BD*DGC*KKC*HWC];         // (dy, dx, mask, 0)
__device__ float  g_wt[DGC*KKC*CGC*COUTC];       // sample weights [g][k][c][o]
__device__ char   g_aih[(size_t)BD*288*9*16384]; // im2col hi, SW128 [px128][k64]
__device__ char   g_ail[(size_t)BD*288*9*16384]; // im2col lo
__device__ char   g_wbh[9*WCHUNK];               // conv W hi chunks [n224][k64] SW128
__device__ char   g_wbl[9*WCHUNK];               // conv W lo chunks

// ---------------- kernel T: repack x0 (8ch contiguous) ----------------------
__global__ void k_transpose(const float* __restrict__ x0) {
    int m = blockIdx.x * blockDim.x + threadIdx.x;
    if (m >= BD*DGC*HWC) return;
    int yx = m % HWC;
    int g  = (m / HWC) % DGC;
    int b  = m / (HWC*DGC);
    const float* src = x0 + ((size_t)(b*CINC + g*8)*HWC) + yx;
    float4 a, c;
    a.x = src[0*HWC]; a.y = src[1*HWC]; a.z = src[2*HWC]; a.w = src[3*HWC];
    c.x = src[4*HWC]; c.y = src[5*HWC]; c.z = src[6*HWC]; c.w = src[7*HWC];
    float4* dst = reinterpret_cast<float4*>(g_x0t + (size_t)m * 8);
    dst[0] = a; dst[1] = c;
}

// ---------------- kernel W: repack sample weight to [g][k][c][o] -------------
__global__ void k_wprep(const float* __restrict__ weight) {
    int m = blockIdx.x * blockDim.x + threadIdx.x;
    if (m >= DGC*KKC*CGC*COUTC) return;
    int o = m & 63;
    int r = m >> 6;
    int c = r & 7;
    int s = r >> 3;
    int k = s % 9, g = s / 9;
    g_wt[m] = weight[(o*CINC + g*8 + c)*KKC + k];
}

// ---------------- kernel WS: conv weights -> hi/lo bf16 chunks ---------------
__global__ void k_wsplit(const float* __restrict__ com_w) {
    int m = blockIdx.x * blockDim.x + threadIdx.x;
    if (m >= 9*NPAD*64) return;
    int ki = m & 63;
    int n  = (m >> 6) % NPAD;
    int cp = m / (NPAD*64);
    float w = 0.f;
    if (n < 216) {
        int kp = cp*64 + ki;
        int cin = kp / 9;
        int tap = kp - cin*9;
        int i = n / 3;
        int r = n - 3*i;
        int ch = (r == 0) ? 2*i : (r == 1) ? (2*i + 1) : (144 + i);
        w = com_w[ch*576 + cin*9 + tap];
    }
    __nv_bfloat16 h = __float2bfloat16(w);
    __nv_bfloat16 l = __float2bfloat16(w - __bfloat162float(h));
    uint32_t byte = (uint32_t)(n*64 + ki)*2;
    uint32_t sw = byte ^ ((byte >> 3) & 0x70);
    *(__nv_bfloat16*)(g_wbh + cp*WCHUNK + sw) = h;
    *(__nv_bfloat16*)(g_wbl + cp*WCHUNK + sw) = l;
}

// ---------------- kernel I: im2col (coalesced warp stores) -------------------
__global__ void __launch_bounds__(256, 1)
k_imcol(const float* __restrict__ x1) {
    __shared__ float xs[CINC*10*19];
    int blk = blockIdx.x;
    int tl  = blk % 288;
    int b   = blk / 288;
    int ty0 = (tl / 12) * 8;
    int tx0 = (tl % 12) * 16;
    int tid = threadIdx.x;

    for (int m = tid; m < CINC*10*18; m += 256) {
        int cin = m / 180;
        int rem = m % 180;
        int r = rem / 18, c = rem % 18;
        int gy = ty0 - 1 + r, gx = tx0 - 1 + c;
        float v = 0.f;
        if (gy >= 0 && gy < HH && gx >= 0 && gx < WW)
            v = x1[((b*CINC + cin)*HWC) + gy*WW + gx];
        xs[cin*190 + r*19 + c] = v;
    }
    __syncthreads();

    size_t base = (size_t)blk * 9 * 16384;
    for (int m = tid; m < 128*576; m += 256) {
        int px = m / 576;            // warp-uniform (576 % 32 == 0)
        int kp = m - px*576;
        int cin = kp / 9;
        int tap = kp - cin*9;
        int ti = tap / 3, tj = tap - ti*3;
        int pr = px >> 4, pc = px & 15;
        float v = xs[cin*190 + (pr + ti)*19 + (pc + tj)];
        __nv_bfloat16 h = __float2bfloat16(v);
        __nv_bfloat16 l = __float2bfloat16(v - __bfloat162float(h));
        int cp = kp >> 6;
        int ki = kp & 63;
        uint32_t byte = (uint32_t)(px*128 + ki*2);
        uint32_t sw = byte ^ ((byte >> 3) & 0x70);
        size_t off = base + (size_t)cp*16384 + sw;
        *(__nv_bfloat16*)(g_aih + off) = h;
        *(__nv_bfloat16*)(g_ail + off) = l;
    }
}

// ---------------- kernel G: HMMA conv GEMM (R11 config: 8 warps, N=224) -----
// grid (288, B), 256 thr. CTA = 128 px x 216(224) ch. warps 2M x 4N:
// warp = 4 m16-tiles x 7 n8-tiles. 3-pass bf16 hi/lo split.
// smem: A 2buf x 2plane x 16KB (0..65535) + W 2buf x 2plane x 28672
//       (65536..180223); epilogue stage [128][228] f32 aliases base.
struct ConvSmem { char bytes[180224]; };

__device__ __forceinline__ void conv_issue(uint32_t sb, int blk, int c, int buf, int tid) {
    size_t ab = ((size_t)(blk*9 + c)) * 16384;
    #pragma unroll
    for (int u = tid; u < 2048; u += 256) {
        int pl = u >> 10, ln = u & 1023;
        uint32_t d = sb + buf*32768 + pl*16384 + ln*16;
        const char* s = (pl ? g_ail : g_aih) + ab + (size_t)ln*16;
        CPASYNC16(d, s);
    }
    #pragma unroll
    for (int u = tid; u < 3584; u += 256) {
        int pl = u / 1792, ln = u % 1792;
        uint32_t d = sb + 65536 + buf*57344 + pl*28672 + ln*16;
        const char* s = (pl ? g_wbl : g_wbh) + c*WCHUNK + (size_t)ln*16;
        CPASYNC16(d, s);
    }
    asm volatile("cp.async.commit_group;" ::: "memory");
}

__device__ __forceinline__ void conv_pass(
    uint32_t Ap, uint32_t Wp,
    float (&acc)[4][7][4],
    const uint32_t (&a_row)[4], const uint32_t (&b_row)[7],
    uint32_t a_kb, uint32_t b_kb, uint32_t a_xor)
{
    #pragma unroll
    for (int ks = 0; ks < 4; ks++) {
        uint32_t kk = (uint32_t)ks * 32;
        uint32_t af[4][4];
        #pragma unroll
        for (int mt = 0; mt < 4; mt++)
            LDM_X4(af[mt], Ap + a_row[mt] + ((kk + a_kb) ^ a_xor));
        uint32_t bf[7][2];
        #pragma unroll
        for (int nt = 0; nt < 7; nt++)
            LDM_X2(bf[nt], Wp + b_row[nt] + ((kk + b_kb) ^ a_xor));
        #pragma unroll
        for (int mt = 0; mt < 4; mt++)
            #pragma unroll
            for (int nt = 0; nt < 7; nt++)
                MMA16816(acc[mt][nt], af[mt], bf[nt]);
    }
}

__global__ void __launch_bounds__(256, 1)
k_conv(const float* __restrict__ com_b,
       const float* __restrict__ pre_off,
       const float* __restrict__ pre_sim) {
    extern __shared__ ConvSmem smc[];
    uint32_t sb = smem_u32(smc);
    int tid  = threadIdx.x;
    int lane = tid & 31, wid = tid >> 5;
    int wm = wid & 1, wn = wid >> 1;
    int b   = blockIdx.y;
    int tl  = blockIdx.x;
    int blk = b*288 + tl;
    int ty0 = (tl / 12) * 8;
    int tx0 = (tl % 12) * 16;

    uint32_t a_xor = (lane & 7) << 4;
    uint32_t a_kb  = (lane >> 4) << 4;
    uint32_t b_kb  = ((lane >> 3) & 1) << 4;
    uint32_t a_row[4], b_row[7];
    #pragma unroll
    for (int mt = 0; mt < 4; mt++)
        a_row[mt] = (uint32_t)(wm*64 + mt*16 + (lane & 15)) * 128;
    #pragma unroll
    for (int nt = 0; nt < 7; nt++)
        b_row[nt] = (uint32_t)(wn*56 + nt*8 + (lane & 7)) * 128;

    float acc[4][7][4];
    #pragma unroll
    for (int mt = 0; mt < 4; mt++)
        #pragma unroll
        for (int nt = 0; nt < 7; nt++)
            #pragma unroll
            for (int q = 0; q < 4; q++) acc[mt][nt][q] = 0.f;

    conv_issue(sb, blk, 0, 0, tid);

    for (int c = 0; c < 9; c++) {
        int buf = c & 1;
        if (c < 8) {
            conv_issue(sb, blk, c + 1, buf ^ 1, tid);
            asm volatile("cp.async.wait_group 1;" ::: "memory");
        } else {
            asm volatile("cp.async.wait_group 0;" ::: "memory");
        }
        __syncthreads();

        uint32_t Ah = sb + buf*32768;
        uint32_t Al = Ah + 16384;
        uint32_t Wh = sb + 65536 + buf*57344;
        uint32_t Wl = Wh + 28672;

        conv_pass(Ah, Wh, acc, a_row, b_row, a_kb, b_kb, a_xor);
        conv_pass(Ah, Wl, acc, a_row, b_row, a_kb, b_kb, a_xor);
        conv_pass(Al, Wh, acc, a_row, b_row, a_kb, b_kb, a_xor);

        __syncthreads();
    }

    float* os = (float*)smc;
    int gid = lane >> 2, tig = lane & 3;
    #pragma unroll
    for (int mt = 0; mt < 4; mt++) {
        int m0 = wm*64 + mt*16 + gid;
        #pragma unroll
        for (int nt = 0; nt < 7; nt++) {
            int n0 = wn*56 + nt*8 + tig*2;
            *(float2*)&os[m0*228 + n0]       = make_float2(acc[mt][nt][0], acc[mt][nt][1]);
            *(float2*)&os[(m0 + 8)*228 + n0] = make_float2(acc[mt][nt][2], acc[mt][nt][3]);
        }
    }
    __syncthreads();

    for (int it = tid; it < 128*72; it += 256) {
        int px = it & 127;
        int i  = it >> 7;
        int k  = i % 9;
        int y  = ty0 + (px >> 4);
        int x  = tx0 + (px & 15);
        float o1 = os[px*228 + 3*i]     + com_b[2*i];
        float o2 = os[px*228 + 3*i + 1] + com_b[2*i + 1];
        float mr = os[px*228 + 3*i + 2] + com_b[144 + i];
        float2 po = ((const float2*)pre_off)[(b*9 + k)*HWC + y*WW + x];
        float dy = 10.f * tanhf(o1) + po.y;
        float dx = 10.f * tanhf(o2) + po.x;
        int idx = (b*72 + i)*HWC + y*WW + x;
        float sim = pre_sim[idx];
        float msk = 1.f / (1.f + expf(-mr * sim));
        g_par[idx] = make_float4(dy, dx, msk, 0.f);
    }
}

// ---------------- kernel S: sample + reduce; low-pressure q-outer reduce ----
__global__ void __launch_bounds__(256, 2)
k_sample(const float* __restrict__ bias,
         float* __restrict__ out) {
    extern __shared__ float sm[];
    float* xs  = sm;                    // [RR][RP][8]
    float* wsl = sm + RR*RP*8;          // [k][c][o]

    int b    = blockIdx.y;
    int tile = blockIdx.x;
    int ty0  = (tile / 12) * 16;
    int tx0  = (tile % 12) * 16;
    int tid  = threadIdx.x;
    int ty = tid >> 4, tx = tid & 15;
    int y = ty0 + ty, x = tx0 + tx;
    int ry0 = ty0 - RG, rx0 = tx0 - RG;

    u64 acc[32];
    #pragma unroll
    for (int q = 0; q < 32; q++) acc[q] = 0ull;

    for (int g = 0; g < DGC; g++) {
        const float* xb = g_x0t + (size_t)(b*DGC + g) * HWC * CGC;
        float4 prc = g_par[((b*72 + g*9)*HWC) + y*WW + x];
        __syncthreads();
        {
            const float4* wsrc = reinterpret_cast<const float4*>(g_wt + g*4608);
            float4* wdst = reinterpret_cast<float4*>(wsl);
            for (int m = tid; m < 1152; m += 256) wdst[m] = wsrc[m];
        }
        for (int m = tid; m < RR*RR*2; m += 256) {
            int cell = m >> 1, hh = m & 1;
            int rr = cell / RR, cc = cell % RR;
            int gy = ry0 + rr, gx = rx0 + cc;
            float4 v = make_float4(0.f, 0.f, 0.f, 0.f);
            if (gy >= 0 && gy < HH && gx >= 0 && gx < WW)
                v = *reinterpret_cast<const float4*>(xb + (size_t)(gy*WW + gx)*8 + hh*4);
            *reinterpret_cast<float4*>(xs + (rr*RP + cc)*8 + hh*4) = v;
        }
        __syncthreads();

        #pragma unroll 1
        for (int k = 0; k < KKC; k++) {
            int kn = (k < 8) ? (k + 1) : 8;
            float4 prn = g_par[((b*72 + g*9 + kn)*HWC) + y*WW + x];

            float dy = prc.x, dx = prc.y, mk = prc.z;
            float py = (float)(y - 1 + k/3) + dy;
            float px = (float)(x - 1 + k%3) + dx;
            float y0f = floorf(py), x0f = floorf(px);
            float ly = py - y0f,   lx = px - x0f;
            int iy0 = (int)y0f, ix0 = (int)x0f;

            u64 sv2[4] = {0ull, 0ull, 0ull, 0ull};
            #pragma unroll
            for (int cy = 0; cy < 2; cy++) {
                int yy = iy0 + cy;
                float wy = cy ? ly : (1.f - ly);
                #pragma unroll
                for (int cx = 0; cx < 2; cx++) {
                    int xx = ix0 + cx;
                    u64 wg2 = pk2(wy * (cx ? lx : (1.f - lx)));
                    int ry = yy - ry0, rx = xx - rx0;
                    if ((unsigned)ry < RR && (unsigned)rx < RR) {
                        const ulonglong2* pp =
                            reinterpret_cast<const ulonglong2*>(xs + (ry*RP + rx)*8);
                        ulonglong2 v0 = pp[0];
                        ulonglong2 v1 = pp[1];
                        fma2(sv2[0], wg2, v0.x);
                        fma2(sv2[1], wg2, v0.y);
                        fma2(sv2[2], wg2, v1.x);
                        fma2(sv2[3], wg2, v1.y);
                    } else if (yy >= 0 && yy < HH && xx >= 0 && xx < WW) {
                        const ulonglong2* pp =
                            reinterpret_cast<const ulonglong2*>(xb + (size_t)(yy*WW + xx)*8);
                        ulonglong2 v0 = pp[0];
                        ulonglong2 v1 = pp[1];
                        fma2(sv2[0], wg2, v0.x);
                        fma2(sv2[1], wg2, v0.y);
                        fma2(sv2[2], wg2, v1.x);
                        fma2(sv2[3], wg2, v1.y);
                    }
                }
            }

            u64 s2[8];
            #pragma unroll
            for (int c = 0; c < 8; c++) {
                u64 hv = sv2[c >> 1];
                float s = ((c & 1) ? hi32(hv) : lo32(hv)) * mk;
                s2[c] = pk2(s);
            }

            const float* wrow = wsl + k*512;
            #pragma unroll
            for (int q4 = 0; q4 < 16; q4++) {
                #pragma unroll
                for (int c = 0; c < 8; c++) {
                    ulonglong2 w = *reinterpret_cast<const ulonglong2*>(
                        wrow + c*64 + 4*q4);
                    fma2(acc[2*q4],     s2[c], w.x);
                    fma2(acc[2*q4 + 1], s2[c], w.y);
                }
            }
            prc = prn;
        }
    }

    #pragma unroll
    for (int q = 0; q < 32; q++) {
        out[((b*COUTC + 2*q)    *HH + y)*WW + x] = lo32(acc[q]) + bias[2*q];
        out[((b*COUTC + 2*q + 1)*HH + y)*WW + x] = hi32(acc[q]) + bias[2*q+1];
    }
}

// ---------------- launch ----------------------------------------------------
// Order chosen so k_conv is the 4th launch (index 3) — the slot ncu captures.
extern "C" void kernel_launch(void* const* d_in, const int* in_sizes, int n_in,
                              void* d_out, int out_size) {
    const float* x0      = (const float*)d_in[0];
    const float* x1      = (const float*)d_in[1];
    const float* pre_off = (const float*)d_in[2];
    const float* pre_sim = (const float*)d_in[3];
    const float* weight  = (const float*)d_in[4];
    const float* bias    = (const float*)d_in[5];
    const float* com_w   = (const float*)d_in[6];
    const float* com_b   = (const float*)d_in[7];
    float* out = (float*)d_out;

    cudaFuncSetAttribute(k_conv,   cudaFuncAttributeMaxDynamicSharedMemorySize, 180224);
    cudaFuncSetAttribute(k_sample, cudaFuncAttributeMaxDynamicSharedMemorySize, 70912);

    k_wprep<<<(DGC*KKC*CGC*COUTC + 255) / 256, 256>>>(weight);
    k_wsplit<<<(9*NPAD*64 + 255) / 256, 256>>>(com_w);
    k_imcol<<<BD*288, 256>>>(x1);

    dim3 gridG(288, BD);
    k_conv<<<gridG, 256, 180224>>>(com_b, pre_off, pre_sim);

    int totalT = BD*DGC*HWC;
    k_transpose<<<(totalT + 255) / 256, 256>>>(x0);

    dim3 gridS(144, BD);
    k_sample<<<gridS, 256, 70912>>>(bias, out);
}

// round 16
// speedup vs baseline: 1.1403x; 1.0327x over previous
#include <cuda_runtime.h>
#include <cuda_bf16.h>
#include <math.h>
#include <stdint.h>

#define BD   2
#define CINC 64
#define COUTC 64
#define HH   192
#define WW   192
#define DGC  8
#define CGC  8
#define KKC  9
#define HWC  (HH*WW)

#define RR 40     // staging region (16 + 2*RG)
#define RP 41     // padded row stride in cells
#define RG 12     // guard; global fallback covers |offset| > RG-1

#define NPAD 224            // conv N padded: 216 real rows + 8 zero rows
#define WCHUNK (NPAD*64*2)  // 28672 B per weight chunk plane

typedef unsigned long long u64;

__device__ __forceinline__ u64 pk2(float v) {
    u64 r; asm("mov.b64 %0, {%1,%1};" : "=l"(r) : "f"(v)); return r;
}
__device__ __forceinline__ void fma2(u64 &d, u64 a, u64 b) {
    asm("fma.rn.f32x2 %0, %1, %2, %0;" : "+l"(d) : "l"(a), "l"(b));
}
__device__ __forceinline__ float lo32(u64 v) { return __uint_as_float((unsigned)v); }
__device__ __forceinline__ float hi32(u64 v) { return __uint_as_float((unsigned)(v >> 32)); }

__device__ __forceinline__ uint32_t smem_u32(const void* p) {
    uint32_t a;
    asm("{ .reg .u64 t; cvta.to.shared.u64 t, %1; cvt.u32.u64 %0, t; }" : "=r"(a) : "l"(p));
    return a;
}

#define LDM_X4(r, addr) \
    asm volatile("ldmatrix.sync.aligned.m8n8.x4.shared.b16 {%0,%1,%2,%3}, [%4];" \
        : "=r"((r)[0]), "=r"((r)[1]), "=r"((r)[2]), "=r"((r)[3]) : "r"(addr))
#define LDM_X2(r, addr) \
    asm volatile("ldmatrix.sync.aligned.m8n8.x2.shared.b16 {%0,%1}, [%2];" \
        : "=r"((r)[0]), "=r"((r)[1]) : "r"(addr))
#define MMA16816(c, a, bb) \
    asm volatile("mma.sync.aligned.m16n8k16.row.col.f32.bf16.bf16.f32 " \
        "{%0,%1,%2,%3},{%4,%5,%6,%7},{%8,%9},{%0,%1,%2,%3};" \
        : "+f"((c)[0]), "+f"((c)[1]), "+f"((c)[2]), "+f"((c)[3]) \
        : "r"((a)[0]), "r"((a)[1]), "r"((a)[2]), "r"((a)[3]), \
          "r"((bb)[0]), "r"((bb)[1]))
#define CPASYNC16(dst, src) \
    asm volatile("cp.async.cg.shared.global [%0], [%1], 16;" :: "r"(dst), "l"(src))

// ---------------- scratch ---------------------------------------------------
__device__ float  g_x0t[BD*CINC*HWC];            // x0 repacked [B][DG][H*W][CG]
__device__ float4 g_par[BD*DGC*KKC*HWC];         // (dy, dx, mask, 0)
__device__ float  g_wt[DGC*KKC*CGC*COUTC];       // sample weights [g][k][c][o]
__device__ char   g_aih[(size_t)BD*288*9*16384]; // im2col hi, SW128 [px128][k64]
__device__ char   g_ail[(size_t)BD*288*9*16384]; // im2col lo
__device__ char   g_wbh[9*WCHUNK];               // conv W hi chunks [n224][k64] SW128
__device__ char   g_wbl[9*WCHUNK];               // conv W lo chunks

// ---------------- kernel T: repack x0 (8ch contiguous) ----------------------
__global__ void k_transpose(const float* __restrict__ x0) {
    int m = blockIdx.x * blockDim.x + threadIdx.x;
    if (m >= BD*DGC*HWC) return;
    int yx = m % HWC;
    int g  = (m / HWC) % DGC;
    int b  = m / (HWC*DGC);
    const float* src = x0 + ((size_t)(b*CINC + g*8)*HWC) + yx;
    float4 a, c;
    a.x = src[0*HWC]; a.y = src[1*HWC]; a.z = src[2*HWC]; a.w = src[3*HWC];
    c.x = src[4*HWC]; c.y = src[5*HWC]; c.z = src[6*HWC]; c.w = src[7*HWC];
    float4* dst = reinterpret_cast<float4*>(g_x0t + (size_t)m * 8);
    dst[0] = a; dst[1] = c;
}

// ---------------- kernel W: repack sample weight to [g][k][c][o] -------------
__global__ void k_wprep(const float* __restrict__ weight) {
    int m = blockIdx.x * blockDim.x + threadIdx.x;
    if (m >= DGC*KKC*CGC*COUTC) return;
    int o = m & 63;
    int r = m >> 6;
    int c = r & 7;
    int s = r >> 3;
    int k = s % 9, g = s / 9;
    g_wt[m] = weight[(o*CINC + g*8 + c)*KKC + k];
}

// ---------------- kernel WS: conv weights -> hi/lo bf16 chunks ---------------
__global__ void k_wsplit(const float* __restrict__ com_w) {
    int m = blockIdx.x * blockDim.x + threadIdx.x;
    if (m >= 9*NPAD*64) return;
    int ki = m & 63;
    int n  = (m >> 6) % NPAD;
    int cp = m / (NPAD*64);
    float w = 0.f;
    if (n < 216) {
        int kp = cp*64 + ki;
        int cin = kp / 9;
        int tap = kp - cin*9;
        int i = n / 3;
        int r = n - 3*i;
        int ch = (r == 0) ? 2*i : (r == 1) ? (2*i + 1) : (144 + i);
        w = com_w[ch*576 + cin*9 + tap];
    }
    __nv_bfloat16 h = __float2bfloat16(w);
    __nv_bfloat16 l = __float2bfloat16(w - __bfloat162float(h));
    uint32_t byte = (uint32_t)(n*64 + ki)*2;
    uint32_t sw = byte ^ ((byte >> 3) & 0x70);
    *(__nv_bfloat16*)(g_wbh + cp*WCHUNK + sw) = h;
    *(__nv_bfloat16*)(g_wbl + cp*WCHUNK + sw) = l;
}

// ---------------- kernel I: im2col (coalesced warp stores) -------------------
__global__ void __launch_bounds__(256, 1)
k_imcol(const float* __restrict__ x1) {
    __shared__ float xs[CINC*10*19];
    int blk = blockIdx.x;
    int tl  = blk % 288;
    int b   = blk / 288;
    int ty0 = (tl / 12) * 8;
    int tx0 = (tl % 12) * 16;
    int tid = threadIdx.x;

    for (int m = tid; m < CINC*10*18; m += 256) {
        int cin = m / 180;
        int rem = m % 180;
        int r = rem / 18, c = rem % 18;
        int gy = ty0 - 1 + r, gx = tx0 - 1 + c;
        float v = 0.f;
        if (gy >= 0 && gy < HH && gx >= 0 && gx < WW)
            v = x1[((b*CINC + cin)*HWC) + gy*WW + gx];
        xs[cin*190 + r*19 + c] = v;
    }
    __syncthreads();

    size_t base = (size_t)blk * 9 * 16384;
    for (int m = tid; m < 128*576; m += 256) {
        int px = m / 576;            // warp-uniform (576 % 32 == 0)
        int kp = m - px*576;
        int cin = kp / 9;
        int tap = kp - cin*9;
        int ti = tap / 3, tj = tap - ti*3;
        int pr = px >> 4, pc = px & 15;
        float v = xs[cin*190 + (pr + ti)*19 + (pc + tj)];
        __nv_bfloat16 h = __float2bfloat16(v);
        __nv_bfloat16 l = __float2bfloat16(v - __bfloat162float(h));
        int cp = kp >> 6;
        int ki = kp & 63;
        uint32_t byte = (uint32_t)(px*128 + ki*2);
        uint32_t sw = byte ^ ((byte >> 3) & 0x70);
        size_t off = base + (size_t)cp*16384 + sw;
        *(__nv_bfloat16*)(g_aih + off) = h;
        *(__nv_bfloat16*)(g_ail + off) = l;
    }
}

// ---------------- kernel G: HMMA conv GEMM — 16 warps, 4M x 4N, N=224 -------
// grid (288, B), 512 thr. Warp tile = 2 m16 x 7 n8 (acc 56 f32) — low reg
// pressure so ptxas can pipeline ldmatrix ahead of mma; 4 warps/SMSP.
// smem unchanged from R11: A 2x2x16KB + W 2x2x28672 = 180224.
struct ConvSmem { char bytes[180224]; };

__device__ __forceinline__ void conv_issue(uint32_t sb, int blk, int c, int buf, int tid) {
    size_t ab = ((size_t)(blk*9 + c)) * 16384;
    #pragma unroll
    for (int u = tid; u < 2048; u += 512) {
        int pl = u >> 10, ln = u & 1023;
        uint32_t d = sb + buf*32768 + pl*16384 + ln*16;
        const char* s = (pl ? g_ail : g_aih) + ab + (size_t)ln*16;
        CPASYNC16(d, s);
    }
    #pragma unroll
    for (int u = tid; u < 3584; u += 512) {
        int pl = u / 1792, ln = u % 1792;
        uint32_t d = sb + 65536 + buf*57344 + pl*28672 + ln*16;
        const char* s = (pl ? g_wbl : g_wbh) + c*WCHUNK + (size_t)ln*16;
        CPASYNC16(d, s);
    }
    asm volatile("cp.async.commit_group;" ::: "memory");
}

__device__ __forceinline__ void conv_pass(
    uint32_t Ap, uint32_t Wp,
    float (&acc)[2][7][4],
    const uint32_t (&a_row)[2], const uint32_t (&b_row)[7],
    uint32_t a_kb, uint32_t b_kb, uint32_t a_xor)
{
    #pragma unroll
    for (int ks = 0; ks < 4; ks++) {
        uint32_t kk = (uint32_t)ks * 32;
        uint32_t af[2][4];
        #pragma unroll
        for (int mt = 0; mt < 2; mt++)
            LDM_X4(af[mt], Ap + a_row[mt] + ((kk + a_kb) ^ a_xor));
        uint32_t bf[7][2];
        #pragma unroll
        for (int nt = 0; nt < 7; nt++)
            LDM_X2(bf[nt], Wp + b_row[nt] + ((kk + b_kb) ^ a_xor));
        #pragma unroll
        for (int mt = 0; mt < 2; mt++)
            #pragma unroll
            for (int nt = 0; nt < 7; nt++)
                MMA16816(acc[mt][nt], af[mt], bf[nt]);
    }
}

__global__ void __launch_bounds__(512, 1)
k_conv(const float* __restrict__ com_b,
       const float* __restrict__ pre_off,
       const float* __restrict__ pre_sim) {
    extern __shared__ ConvSmem smc[];
    uint32_t sb = smem_u32(smc);
    int tid  = threadIdx.x;
    int lane = tid & 31, wid = tid >> 5;
    int wm = wid & 3, wn = wid >> 2;        // 4M x 4N
    int b   = blockIdx.y;
    int tl  = blockIdx.x;
    int blk = b*288 + tl;
    int ty0 = (tl / 12) * 8;
    int tx0 = (tl % 12) * 16;

    uint32_t a_xor = (lane & 7) << 4;
    uint32_t a_kb  = (lane >> 4) << 4;
    uint32_t b_kb  = ((lane >> 3) & 1) << 4;
    uint32_t a_row[2], b_row[7];
    #pragma unroll
    for (int mt = 0; mt < 2; mt++)
        a_row[mt] = (uint32_t)(wm*32 + mt*16 + (lane & 15)) * 128;
    #pragma unroll
    for (int nt = 0; nt < 7; nt++)
        b_row[nt] = (uint32_t)(wn*56 + nt*8 + (lane & 7)) * 128;

    float acc[2][7][4];
    #pragma unroll
    for (int mt = 0; mt < 2; mt++)
        #pragma unroll
        for (int nt = 0; nt < 7; nt++)
            #pragma unroll
            for (int q = 0; q < 4; q++) acc[mt][nt][q] = 0.f;

    conv_issue(sb, blk, 0, 0, tid);

    for (int c = 0; c < 9; c++) {
        int buf = c & 1;
        if (c < 8) {
            conv_issue(sb, blk, c + 1, buf ^ 1, tid);
            asm volatile("cp.async.wait_group 1;" ::: "memory");
        } else {
            asm volatile("cp.async.wait_group 0;" ::: "memory");
        }
        __syncthreads();

        uint32_t Ah = sb + buf*32768;
        uint32_t Al = Ah + 16384;
        uint32_t Wh = sb + 65536 + buf*57344;
        uint32_t Wl = Wh + 28672;

        conv_pass(Ah, Wh, acc, a_row, b_row, a_kb, b_kb, a_xor);
        conv_pass(Ah, Wl, acc, a_row, b_row, a_kb, b_kb, a_xor);
        conv_pass(Al, Wh, acc, a_row, b_row, a_kb, b_kb, a_xor);

        __syncthreads();
    }

    float* os = (float*)smc;
    int gid = lane >> 2, tig = lane & 3;
    #pragma unroll
    for (int mt = 0; mt < 2; mt++) {
        int m0 = wm*32 + mt*16 + gid;
        #pragma unroll
        for (int nt = 0; nt < 7; nt++) {
            int n0 = wn*56 + nt*8 + tig*2;
            *(float2*)&os[m0*228 + n0]       = make_float2(acc[mt][nt][0], acc[mt][nt][1]);
            *(float2*)&os[(m0 + 8)*228 + n0] = make_float2(acc[mt][nt][2], acc[mt][nt][3]);
        }
    }
    __syncthreads();

    for (int it = tid; it < 128*72; it += 512) {
        int px = it & 127;
        int i  = it >> 7;
        int k  = i % 9;
        int y  = ty0 + (px >> 4);
        int x  = tx0 + (px & 15);
        float o1 = os[px*228 + 3*i]     + com_b[2*i];
        float o2 = os[px*228 + 3*i + 1] + com_b[2*i + 1];
        float mr = os[px*228 + 3*i + 2] + com_b[144 + i];
        float2 po = ((const float2*)pre_off)[(b*9 + k)*HWC + y*WW + x];
        float dy = 10.f * tanhf(o1) + po.y;
        float dx = 10.f * tanhf(o2) + po.x;
        int idx = (b*72 + i)*HWC + y*WW + x;
        float sim = pre_sim[idx];
        float msk = 1.f / (1.f + expf(-mr * sim));
        g_par[idx] = make_float4(dy, dx, msk, 0.f);
    }
}

// ---------------- kernel S: sample + reduce; low-pressure q-outer reduce ----
__global__ void __launch_bounds__(256, 2)
k_sample(const float* __restrict__ bias,
         float* __restrict__ out) {
    extern __shared__ float sm[];
    float* xs  = sm;                    // [RR][RP][8]
    float* wsl = sm + RR*RP*8;          // [k][c][o]

    int b    = blockIdx.y;
    int tile = blockIdx.x;
    int ty0  = (tile / 12) * 16;
    int tx0  = (tile % 12) * 16;
    int tid  = threadIdx.x;
    int ty = tid >> 4, tx = tid & 15;
    int y = ty0 + ty, x = tx0 + tx;
    int ry0 = ty0 - RG, rx0 = tx0 - RG;

    u64 acc[32];
    #pragma unroll
    for (int q = 0; q < 32; q++) acc[q] = 0ull;

    for (int g = 0; g < DGC; g++) {
        const float* xb = g_x0t + (size_t)(b*DGC + g) * HWC * CGC;
        float4 prc = g_par[((b*72 + g*9)*HWC) + y*WW + x];
        __syncthreads();
        {
            const float4* wsrc = reinterpret_cast<const float4*>(g_wt + g*4608);
            float4* wdst = reinterpret_cast<float4*>(wsl);
            for (int m = tid; m < 1152; m += 256) wdst[m] = wsrc[m];
        }
        for (int m = tid; m < RR*RR*2; m += 256) {
            int cell = m >> 1, hh = m & 1;
            int rr = cell / RR, cc = cell % RR;
            int gy = ry0 + rr, gx = rx0 + cc;
            float4 v = make_float4(0.f, 0.f, 0.f, 0.f);
            if (gy >= 0 && gy < HH && gx >= 0 && gx < WW)
                v = *reinterpret_cast<const float4*>(xb + (size_t)(gy*WW + gx)*8 + hh*4);
            *reinterpret_cast<float4*>(xs + (rr*RP + cc)*8 + hh*4) = v;
        }
        __syncthreads();

        #pragma unroll 1
        for (int k = 0; k < KKC; k++) {
            int kn = (k < 8) ? (k + 1) : 8;
            float4 prn = g_par[((b*72 + g*9 + kn)*HWC) + y*WW + x];

            float dy = prc.x, dx = prc.y, mk = prc.z;
            float py = (float)(y - 1 + k/3) + dy;
            float px = (float)(x - 1 + k%3) + dx;
            float y0f = floorf(py), x0f = floorf(px);
            float ly = py - y0f,   lx = px - x0f;
            int iy0 = (int)y0f, ix0 = (int)x0f;

            u64 sv2[4] = {0ull, 0ull, 0ull, 0ull};
            #pragma unroll
            for (int cy = 0; cy < 2; cy++) {
                int yy = iy0 + cy;
                float wy = cy ? ly : (1.f - ly);
                #pragma unroll
                for (int cx = 0; cx < 2; cx++) {
                    int xx = ix0 + cx;
                    u64 wg2 = pk2(wy * (cx ? lx : (1.f - lx)));
                    int ry = yy - ry0, rx = xx - rx0;
                    if ((unsigned)ry < RR && (unsigned)rx < RR) {
                        const ulonglong2* pp =
                            reinterpret_cast<const ulonglong2*>(xs + (ry*RP + rx)*8);
                        ulonglong2 v0 = pp[0];
                        ulonglong2 v1 = pp[1];
                        fma2(sv2[0], wg2, v0.x);
                        fma2(sv2[1], wg2, v0.y);
                        fma2(sv2[2], wg2, v1.x);
                        fma2(sv2[3], wg2, v1.y);
                    } else if (yy >= 0 && yy < HH && xx >= 0 && xx < WW) {
                        const ulonglong2* pp =
                            reinterpret_cast<const ulonglong2*>(xb + (size_t)(yy*WW + xx)*8);
                        ulonglong2 v0 = pp[0];
                        ulonglong2 v1 = pp[1];
                        fma2(sv2[0], wg2, v0.x);
                        fma2(sv2[1], wg2, v0.y);
                        fma2(sv2[2], wg2, v1.x);
                        fma2(sv2[3], wg2, v1.y);
                    }
                }
            }

            u64 s2[8];
            #pragma unroll
            for (int c = 0; c < 8; c++) {
                u64 hv = sv2[c >> 1];
                float s = ((c & 1) ? hi32(hv) : lo32(hv)) * mk;
                s2[c] = pk2(s);
            }

            const float* wrow = wsl + k*512;
            #pragma unroll
            for (int q4 = 0; q4 < 16; q4++) {
                #pragma unroll
                for (int c = 0; c < 8; c++) {
                    ulonglong2 w = *reinterpret_cast<const ulonglong2*>(
                        wrow + c*64 + 4*q4);
                    fma2(acc[2*q4],     s2[c], w.x);
                    fma2(acc[2*q4 + 1], s2[c], w.y);
                }
            }
            prc = prn;
        }
    }

    #pragma unroll
    for (int q = 0; q < 32; q++) {
        out[((b*COUTC + 2*q)    *HH + y)*WW + x] = lo32(acc[q]) + bias[2*q];
        out[((b*COUTC + 2*q + 1)*HH + y)*WW + x] = hi32(acc[q]) + bias[2*q+1];
    }
}

// ---------------- launch ----------------------------------------------------
// Order keeps k_conv at launch index 3 — the slot ncu captures.
extern "C" void kernel_launch(void* const* d_in, const int* in_sizes, int n_in,
                              void* d_out, int out_size) {
    const float* x0      = (const float*)d_in[0];
    const float* x1      = (const float*)d_in[1];
    const float* pre_off = (const float*)d_in[2];
    const float* pre_sim = (const float*)d_in[3];
    const float* weight  = (const float*)d_in[4];
    const float* bias    = (const float*)d_in[5];
    const float* com_w   = (const float*)d_in[6];
    const float* com_b   = (const float*)d_in[7];
    float* out = (float*)d_out;

    cudaFuncSetAttribute(k_conv,   cudaFuncAttributeMaxDynamicSharedMemorySize, 180224);
    cudaFuncSetAttribute(k_sample, cudaFuncAttributeMaxDynamicSharedMemorySize, 70912);

    k_wprep<<<(DGC*KKC*CGC*COUTC + 255) / 256, 256>>>(weight);
    k_wsplit<<<(9*NPAD*64 + 255) / 256, 256>>>(com_w);
    k_imcol<<<BD*288, 256>>>(x1);

    dim3 gridG(288, BD);
    k_conv<<<gridG, 512, 180224>>>(com_b, pre_off, pre_sim);

    int totalT = BD*DGC*HWC;
    k_transpose<<<(totalT + 255) / 256, 256>>>(x0);

    dim3 gridS(144, BD);
    k_sample<<<gridS, 256, 70912>>>(bias, out);
}